// round 14
// baseline (speedup 1.0000x reference)
#include <cuda_runtime.h>
#include <math.h>
#include <stdint.h>

#define E_    32
#define TOPK  6
#define H_    2048
#define I_    1024
#define T_    2048
#define CAP_  768
#define SCALE_ 1.5f

// ---------------- scratch (device globals; no allocation allowed) ----------------
__device__ int   d_cnt[E_];
__device__ int   d_src[E_ * CAP_];        // slot -> token
__device__ int   d_slot[T_ * TOPK];       // e*CAP_+pos, or -1 if dropped
__device__ float d_wt[T_ * TOPK];         // normalized * SCALE_
__device__ float d_xr[(size_t)T_ * H_];             // tf32-rounded x (GEMM A operand)
__device__ float d_inter[(size_t)E_ * CAP_ * I_];   // silu(g)*u per expert (tf32-rounded)
__device__ float d_sinter[(size_t)T_ * I_];         // shared-expert intermediate (tf32-rounded)
__device__ float d_yb[(size_t)E_ * CAP_ * H_];      // expert outputs (f32)

// =================== portable PTX helpers (compute_103-safe, sm_80+) ===================
__device__ __forceinline__ uint32_t smem_u32(const void* p) {
    uint32_t a;
    asm("{ .reg .u64 t; cvta.to.shared.u64 t, %1; cvt.u32.u64 %0, t; }" : "=r"(a) : "l"(p));
    return a;
}
__device__ __forceinline__ uint32_t tf32r(float f) {
    uint32_t r; asm("cvt.rna.tf32.f32 %0, %1;" : "=r"(r) : "f"(f)); return r;
}
__device__ __forceinline__ float tf32f(float f) {
    return __uint_as_float(tf32r(f));
}
__device__ __forceinline__ void cp16(uint32_t saddr, const void* gaddr, bool v) {
    int sz = v ? 16 : 0;
    asm volatile("cp.async.ca.shared.global [%0], [%1], 16, %2;"
                 :: "r"(saddr), "l"(gaddr), "r"(sz) : "memory");
}
#define CP_COMMIT() asm volatile("cp.async.commit_group;" ::: "memory")
#define CP_WAIT1()  asm volatile("cp.async.wait_group 1;" ::: "memory")
#define CP_WAIT0()  asm volatile("cp.async.wait_group 0;" ::: "memory")

__device__ __forceinline__ void mma_tf32(float* c, const uint32_t* a, const uint32_t* b) {
    asm volatile(
        "mma.sync.aligned.m16n8k8.row.col.f32.tf32.tf32.f32 "
        "{%0,%1,%2,%3}, {%4,%5,%6,%7}, {%8,%9}, {%0,%1,%2,%3};"
        : "+f"(c[0]), "+f"(c[1]), "+f"(c[2]), "+f"(c[3])
        : "r"(a[0]), "r"(a[1]), "r"(a[2]), "r"(a[3]), "r"(b[0]), "r"(b[1]));
}

// ---------------- init ----------------
__global__ void init_kernel() {
    if (threadIdx.x < E_) d_cnt[threadIdx.x] = 0;
}

// ---------------- pre-round x to tf32 (A operand) ----------------
__global__ void round_x_kernel(const float* __restrict__ x) {
    int i = blockIdx.x * blockDim.x + threadIdx.x;   // over float4s
    float4 v = ((const float4*)x)[i];
    float4 o = make_float4(tf32f(v.x), tf32f(v.y), tf32f(v.z), tf32f(v.w));
    ((float4*)d_xr)[i] = o;
}

// ---------------- router ----------------
__global__ void router_kernel(const float* __restrict__ x,
                              const float* __restrict__ gw,
                              const float* __restrict__ bias) {
    int t = blockIdx.x;
    const float4* h4 = (const float4*)(x + (size_t)t * H_);
    __shared__ float sc[E_];
    __shared__ float sb[E_];
    int warp = threadIdx.x >> 5, lane = threadIdx.x & 31;

    for (int e = warp; e < E_; e += 4) {
        const float4* w4 = (const float4*)(gw + (size_t)e * H_);
        float s = 0.f;
        for (int i = lane; i < H_ / 4; i += 32) {
            float4 a = h4[i], b = w4[i];
            s += a.x * b.x + a.y * b.y + a.z * b.z + a.w * b.w;
        }
        #pragma unroll
        for (int o = 16; o > 0; o >>= 1) s += __shfl_xor_sync(0xffffffffu, s, o);
        if (lane == 0) {
            float sp = (s > 15.f) ? s : log1pf(expf(s));
            sc[e] = sqrtf(sp);
        }
    }
    __syncthreads();
    if (threadIdx.x < E_) sb[threadIdx.x] = sc[threadIdx.x] + bias[threadIdx.x];
    __syncthreads();

    if (threadIdx.x == 0) {
        int   idx[TOPK];
        float wsum = 0.f;
        for (int k = 0; k < TOPK; k++) {
            int best = 0; float bv = -1e30f;
            for (int e = 0; e < E_; e++)
                if (sb[e] > bv) { bv = sb[e]; best = e; }
            idx[k] = best;
            sb[best] = -1e30f;
            wsum += sc[best];
        }
        float inv = SCALE_ / wsum;
        for (int k = 0; k < TOPK; k++) {
            int e = idx[k];
            int pos = atomicAdd(&d_cnt[e], 1);
            if (pos < CAP_) {
                d_slot[t * TOPK + k] = e * CAP_ + pos;
                d_src[e * CAP_ + pos] = t;
            } else {
                d_slot[t * TOPK + k] = -1;
            }
            d_wt[t * TOPK + k] = sc[e] * inv;
        }
    }
}

// =================== tf32 mma.sync GEMM (3-stage cp.async pipeline) ===================
// FUSED=1: CTA computes G,U [128 x 64] = A[128,K=2048] @ {Bg,Bu}^T, SwiGLU -> d_inter/d_sinter
//          A = d_xr (pre-rounded). B smem rows 0..63 = Bg, 64..127 = Bu.
// FUSED=0: CTA computes C [128 x 128] = A[128,K=1024] @ B^T (down) -> d_yb / out
//          A = d_inter/d_sinter (stored pre-rounded).
// 8 warps (2m x 4n). smem [row][k] pitch 36 floats, 3 stages, cp.async 2 chunks ahead.

#define PITCH 36
#define STAGE_FLOATS (128 * PITCH)            // 4608 per operand
#define STAGE_BYTES  (2 * STAGE_FLOATS * 4)   // 36864 (A + B)
#define NSTAGE 3
#define SMEM_GEMM    (NSTAGE * STAGE_BYTES)   // 110592 -> 2 CTAs/SM (221KB < 228KB)

template<bool FUSED>
__global__ __launch_bounds__(256, 2)
void gemm_tc(const float* __restrict__ wR1, const float* __restrict__ wR2,
             const float* __restrict__ wS1, const float* __restrict__ wS2,
             float* __restrict__ out)
{
    constexpr int Kd = FUSED ? H_ : I_;
    constexpr int Nd = FUSED ? I_ : H_;
    constexpr int C  = Kd / 32;
    constexpr int NO = FUSED ? 2 : 1;
    constexpr int NT = FUSED ? 2 : 4;

    const int e = blockIdx.z;
    const bool sh = (e == E_);
    const int M = sh ? T_ : min(d_cnt[e], CAP_);
    const int m0 = blockIdx.y * 128;
    if (m0 >= M) return;
    const int n0 = blockIdx.x * (FUSED ? 64 : 128);

    const float* Asrc; const float* B1; const float* B2 = nullptr; float* Cp;
    if (FUSED) {
        Asrc = d_xr;
        B1 = sh ? wS1 : wR1 + (size_t)e * Nd * Kd;   // gate
        B2 = sh ? wS2 : wR2 + (size_t)e * Nd * Kd;   // up
        Cp = sh ? d_sinter : d_inter + (size_t)e * CAP_ * Nd;
    } else {
        Asrc = sh ? d_sinter : d_inter + (size_t)e * CAP_ * Kd;
        B1 = sh ? wS1 : wR1 + (size_t)e * Nd * Kd;
        Cp = sh ? out : d_yb + (size_t)e * CAP_ * Nd;
    }

    extern __shared__ char dsm[];
    __shared__ int srow[128];

    const int tid = threadIdx.x;
    const int wid = tid >> 5, lane = tid & 31;
    const int wr = wid >> 2, wc = wid & 3;       // warp 2x4 grid
    const int g = lane >> 2, tig = lane & 3;

    const bool gath = FUSED && !sh;
    if (gath && tid < 128) srow[tid] = (m0 + tid < M) ? d_src[e * CAP_ + m0 + tid] : 0;
    __syncthreads();

    const uint32_t smem_base = smem_u32(dsm);

    // ---- chunk loader: A and B tiles (128 rows x 32 k) via cp.async ----
    auto load_chunk = [&](int kt, int s) {
        const uint32_t sa = smem_base + (uint32_t)s * STAGE_BYTES;
        const uint32_t sbB = sa + STAGE_FLOATS * 4;
        #pragma unroll
        for (int q = 0; q < 4; q++) {
            int idx = tid + q * 256;
            int row = idx >> 3, c4 = idx & 7;
            // A
            int gr = m0 + row;
            bool v = gr < M;
            const float* gp;
            if (gath) gp = Asrc + (size_t)srow[row] * Kd + kt + c4 * 4;
            else      gp = Asrc + (size_t)(v ? gr : m0) * Kd + kt + c4 * 4;
            cp16(sa + (uint32_t)(row * PITCH + c4 * 4) * 4, gp, v);
            // B (FUSED: rows 0..63 gate, 64..127 up)
            const float* gb;
            if (FUSED) gb = (row < 64 ? B1 + (size_t)(n0 + row) * Kd
                                      : B2 + (size_t)(n0 + row - 64) * Kd) + kt + c4 * 4;
            else       gb = B1 + (size_t)(n0 + row) * Kd + kt + c4 * 4;
            cp16(sbB + (uint32_t)(row * PITCH + c4 * 4) * 4, gb, true);
        }
    };

    float acc[NO][4][NT][4];
    #pragma unroll
    for (int o = 0; o < NO; o++)
        #pragma unroll
        for (int mt = 0; mt < 4; mt++)
            #pragma unroll
            for (int nt = 0; nt < NT; nt++)
                #pragma unroll
                for (int r = 0; r < 4; r++) acc[o][mt][nt][r] = 0.f;

    // prologue: 2 chunks in flight
    load_chunk(0, 0);
    CP_COMMIT();
    load_chunk(32, 1);
    CP_COMMIT();

    int s = 0;
    for (int c = 0; c < C; c++) {
        // wait for chunk c's group; on the last chunk drain fully
        if (c == C - 1) { CP_WAIT0(); } else { CP_WAIT1(); }
        __syncthreads();
        // issue chunk c+2 into stage (s+2)%3 — safe: stage (s+2)%3 held chunk c-1,
        // whose mma finished before this barrier (program order + barrier).
        if (c + 2 < C) {
            int s2 = s + 2 >= NSTAGE ? s + 2 - NSTAGE : s + 2;
            load_chunk((c + 2) * 32, s2);
            CP_COMMIT();
        }

        const float* As = (const float*)(dsm + (size_t)s * STAGE_BYTES);
        const float* Bs = As + STAGE_FLOATS;
        #pragma unroll
        for (int ks = 0; ks < 4; ks++) {
            uint32_t a[4][4];
            #pragma unroll
            for (int mt = 0; mt < 4; mt++) {
                int base = (wr * 64 + mt * 16 + g) * PITCH + ks * 8 + tig;
                // A is pre-rounded tf32: raw bit loads, no cvt
                a[mt][0] = __float_as_uint(As[base]);
                a[mt][1] = __float_as_uint(As[base + 8 * PITCH]);
                a[mt][2] = __float_as_uint(As[base + 4]);
                a[mt][3] = __float_as_uint(As[base + 8 * PITCH + 4]);
            }
            uint32_t b[NO][NT][2];
            #pragma unroll
            for (int o = 0; o < NO; o++)
                #pragma unroll
                for (int nt = 0; nt < NT; nt++) {
                    int brow = FUSED ? (o * 64 + wc * 16 + nt * 8 + g)
                                     : (wc * 32 + nt * 8 + g);
                    int base = brow * PITCH + ks * 8 + tig;
                    b[o][nt][0] = tf32r(Bs[base]);
                    b[o][nt][1] = tf32r(Bs[base + 4]);
                }
            #pragma unroll
            for (int o = 0; o < NO; o++)
                #pragma unroll
                for (int mt = 0; mt < 4; mt++)
                    #pragma unroll
                    for (int nt = 0; nt < NT; nt++)
                        mma_tf32(acc[o][mt][nt], a[mt], b[o][nt]);
        }
        s = (s + 1 >= NSTAGE) ? 0 : s + 1;
    }

    // ---- epilogue ----
    #pragma unroll
    for (int mt = 0; mt < 4; mt++) {
        #pragma unroll
        for (int nt = 0; nt < NT; nt++) {
            int r0 = m0 + wr * 64 + mt * 16 + g;
            int col = n0 + wc * (FUSED ? 16 : 32) + nt * 8 + 2 * tig;
            #pragma unroll
            for (int h = 0; h < 2; h++) {
                int r = r0 + 8 * h;
                if (r >= M) continue;
                if (FUSED) {
                    float gg0 = acc[0][mt][nt][2 * h + 0];
                    float gg1 = acc[0][mt][nt][2 * h + 1];
                    float uu0 = acc[1][mt][nt][2 * h + 0];
                    float uu1 = acc[1][mt][nt][2 * h + 1];
                    float s0 = gg0 / (1.f + expf(-gg0)) * uu0;
                    float s1 = gg1 / (1.f + expf(-gg1)) * uu1;
                    if (sh) {
                        s0 = fminf(fmaxf(s0, -10.f), 10.f);
                        s1 = fminf(fmaxf(s1, -10.f), 10.f);
                    }
                    // store pre-rounded: down pass reads A without cvt (numerically identical)
                    *(float2*)(Cp + (size_t)r * Nd + col) = make_float2(tf32f(s0), tf32f(s1));
                } else {
                    *(float2*)(Cp + (size_t)r * Nd + col) =
                        make_float2(acc[0][mt][nt][2 * h + 0], acc[0][mt][nt][2 * h + 1]);
                }
            }
        }
    }
}

// ---------------- combine: out[t] = shared(out) + sum_k w * yb[slot] ----------------
__global__ void combine_kernel(float* __restrict__ out) {
    int t = blockIdx.x;
    __shared__ int   ss[TOPK];
    __shared__ float sw[TOPK];
    if (threadIdx.x < TOPK) {
        ss[threadIdx.x] = d_slot[t * TOPK + threadIdx.x];
        sw[threadIdx.x] = d_wt[t * TOPK + threadIdx.x];
    }
    __syncthreads();
    float4* orow = (float4*)(out + (size_t)t * H_);
    for (int i = threadIdx.x; i < H_ / 4; i += blockDim.x) {
        float4 o = orow[i];
        #pragma unroll
        for (int k = 0; k < TOPK; k++) {
            int slot = ss[k];
            if (slot < 0) continue;
            float w = sw[k];
            float4 y = ((const float4*)(d_yb + (size_t)slot * H_))[i];
            o.x += w * y.x; o.y += w * y.y; o.z += w * y.z; o.w += w * y.w;
        }
        orow[i] = o;
    }
}

// ---------------- launch ----------------
extern "C" void kernel_launch(void* const* d_in, const int* in_sizes, int n_in,
                              void* d_out, int out_size) {
    const float* x      = (const float*)d_in[0];
    const float* gate_w = (const float*)d_in[1];
    const float* bias   = (const float*)d_in[2];
    const float* w_gate = (const float*)d_in[3];
    const float* w_up   = (const float*)d_in[4];
    const float* w_down = (const float*)d_in[5];
    const float* sg     = (const float*)d_in[6];
    const float* su     = (const float*)d_in[7];
    const float* sd     = (const float*)d_in[8];
    float* out = (float*)d_out;

    cudaFuncSetAttribute(gemm_tc<true>,  cudaFuncAttributeMaxDynamicSharedMemorySize, SMEM_GEMM);
    cudaFuncSetAttribute(gemm_tc<false>, cudaFuncAttributeMaxDynamicSharedMemorySize, SMEM_GEMM);

    init_kernel<<<1, 32>>>();
    round_x_kernel<<<(T_ * H_ / 4) / 256, 256>>>(x);
    router_kernel<<<T_, 128>>>(x, gate_w, bias);

    // fused gate+up (SwiGLU), then down — routed e=0..31 + shared e=32
    gemm_tc<true><<<dim3(I_ / 64, T_ / 128, E_ + 1), 256, SMEM_GEMM>>>(w_gate, w_up, sg, su, nullptr);
    gemm_tc<false><<<dim3(H_ / 128, T_ / 128, E_ + 1), 256, SMEM_GEMM>>>(w_down, nullptr, sd, nullptr, out);

    combine_kernel<<<T_, 256>>>(out);
}

// round 16
// speedup vs baseline: 1.2405x; 1.2405x over previous
#include <cuda_runtime.h>
#include <math.h>
#include <stdint.h>

#define E_    32
#define TOPK  6
#define H_    2048
#define I_    1024
#define T_    2048
#define CAP_  768
#define SCALE_ 1.5f

// ---------------- scratch (device globals; no allocation allowed) ----------------
__device__ int   d_cnt[E_];
__device__ int   d_src[E_ * CAP_];        // slot -> token
__device__ int   d_slot[T_ * TOPK];       // e*CAP_+pos, or -1 if dropped
__device__ float d_wt[T_ * TOPK];         // normalized * SCALE_
__device__ float d_xr[(size_t)T_ * H_];             // tf32-rounded x (GEMM A operand)
__device__ float d_inter[(size_t)E_ * CAP_ * I_];   // silu(g)*u per expert (tf32-rounded)
__device__ float d_sinter[(size_t)T_ * I_];         // shared-expert intermediate (tf32-rounded)
__device__ float d_yb[(size_t)E_ * CAP_ * H_];      // expert outputs (f32)

// =================== portable PTX helpers (compute_103-safe, sm_80+) ===================
__device__ __forceinline__ uint32_t smem_u32(const void* p) {
    uint32_t a;
    asm("{ .reg .u64 t; cvta.to.shared.u64 t, %1; cvt.u32.u64 %0, t; }" : "=r"(a) : "l"(p));
    return a;
}
__device__ __forceinline__ uint32_t tf32r(float f) {
    uint32_t r; asm("cvt.rna.tf32.f32 %0, %1;" : "=r"(r) : "f"(f)); return r;
}
__device__ __forceinline__ uint32_t tf32ru(uint32_t u) {
    uint32_t r; asm("cvt.rna.tf32.f32 %0, %1;" : "=r"(r) : "f"(__uint_as_float(u))); return r;
}
__device__ __forceinline__ float tf32f(float f) {
    return __uint_as_float(tf32r(f));
}
__device__ __forceinline__ void cp16(uint32_t saddr, const void* gaddr, bool v) {
    int sz = v ? 16 : 0;
    asm volatile("cp.async.ca.shared.global [%0], [%1], 16, %2;"
                 :: "r"(saddr), "l"(gaddr), "r"(sz) : "memory");
}
#define CP_COMMIT() asm volatile("cp.async.commit_group;" ::: "memory")
#define CP_WAIT1()  asm volatile("cp.async.wait_group 1;" ::: "memory")
#define CP_WAIT0()  asm volatile("cp.async.wait_group 0;" ::: "memory")

__device__ __forceinline__ void ldsm_x4(uint32_t& r0, uint32_t& r1, uint32_t& r2, uint32_t& r3,
                                        uint32_t addr) {
    asm volatile("ldmatrix.sync.aligned.m8n8.x4.shared.b16 {%0,%1,%2,%3}, [%4];"
                 : "=r"(r0), "=r"(r1), "=r"(r2), "=r"(r3) : "r"(addr));
}
__device__ __forceinline__ void mma_tf32(float* c, const uint32_t* a, const uint32_t* b) {
    asm volatile(
        "mma.sync.aligned.m16n8k8.row.col.f32.tf32.tf32.f32 "
        "{%0,%1,%2,%3}, {%4,%5,%6,%7}, {%8,%9}, {%0,%1,%2,%3};"
        : "+f"(c[0]), "+f"(c[1]), "+f"(c[2]), "+f"(c[3])
        : "r"(a[0]), "r"(a[1]), "r"(a[2]), "r"(a[3]), "r"(b[0]), "r"(b[1]));
}

// ---------------- init ----------------
__global__ void init_kernel() {
    if (threadIdx.x < E_) d_cnt[threadIdx.x] = 0;
}

// ---------------- pre-round x to tf32 (A operand) ----------------
__global__ void round_x_kernel(const float* __restrict__ x) {
    int i = blockIdx.x * blockDim.x + threadIdx.x;   // over float4s
    float4 v = ((const float4*)x)[i];
    float4 o = make_float4(tf32f(v.x), tf32f(v.y), tf32f(v.z), tf32f(v.w));
    ((float4*)d_xr)[i] = o;
}

// ---------------- router ----------------
__global__ void router_kernel(const float* __restrict__ x,
                              const float* __restrict__ gw,
                              const float* __restrict__ bias) {
    int t = blockIdx.x;
    const float4* h4 = (const float4*)(x + (size_t)t * H_);
    __shared__ float sc[E_];
    __shared__ float sb[E_];
    int warp = threadIdx.x >> 5, lane = threadIdx.x & 31;

    for (int e = warp; e < E_; e += 4) {
        const float4* w4 = (const float4*)(gw + (size_t)e * H_);
        float s = 0.f;
        for (int i = lane; i < H_ / 4; i += 32) {
            float4 a = h4[i], b = w4[i];
            s += a.x * b.x + a.y * b.y + a.z * b.z + a.w * b.w;
        }
        #pragma unroll
        for (int o = 16; o > 0; o >>= 1) s += __shfl_xor_sync(0xffffffffu, s, o);
        if (lane == 0) {
            float sp = (s > 15.f) ? s : log1pf(expf(s));
            sc[e] = sqrtf(sp);
        }
    }
    __syncthreads();
    if (threadIdx.x < E_) sb[threadIdx.x] = sc[threadIdx.x] + bias[threadIdx.x];
    __syncthreads();

    if (threadIdx.x == 0) {
        int   idx[TOPK];
        float wsum = 0.f;
        for (int k = 0; k < TOPK; k++) {
            int best = 0; float bv = -1e30f;
            for (int e = 0; e < E_; e++)
                if (sb[e] > bv) { bv = sb[e]; best = e; }
            idx[k] = best;
            sb[best] = -1e30f;
            wsum += sc[best];
        }
        float inv = SCALE_ / wsum;
        for (int k = 0; k < TOPK; k++) {
            int e = idx[k];
            int pos = atomicAdd(&d_cnt[e], 1);
            if (pos < CAP_) {
                d_slot[t * TOPK + k] = e * CAP_ + pos;
                d_src[e * CAP_ + pos] = t;
            } else {
                d_slot[t * TOPK + k] = -1;
            }
            d_wt[t * TOPK + k] = sc[e] * inv;
        }
    }
}

// =================== tf32 mma.sync GEMM (R8 pipeline + ldmatrix fragments) ===================
// FUSED=1: CTA computes G,U [128 x 64] = A[128,K=2048] @ {Bg,Bu}^T, SwiGLU -> d_inter/d_sinter
// FUSED=0: CTA computes C [128 x 128] = A[128,K=1024] @ B^T (down) -> d_yb / out
// 8 warps (2m x 4n). smem [row][k] pitch 36 floats, 2 stages, cp.async-fed.
// Fragments loaded with ldmatrix.x4 (b16 view; each reg = one float; row t/4, col t%4
// distribution matches the tf32 mma operand layout exactly).

#define PITCH 36
#define STAGE_FLOATS (128 * PITCH)            // 4608 per operand
#define STAGE_BYTES  (2 * STAGE_FLOATS * 4)   // 36864 (A + B)
#define SMEM_GEMM    (2 * STAGE_BYTES)        // 73728 -> 2 CTAs/SM

template<bool FUSED>
__global__ __launch_bounds__(256, 2)
void gemm_tc(const float* __restrict__ wR1, const float* __restrict__ wR2,
             const float* __restrict__ wS1, const float* __restrict__ wS2,
             float* __restrict__ out)
{
    constexpr int Kd = FUSED ? H_ : I_;
    constexpr int Nd = FUSED ? I_ : H_;
    constexpr int C  = Kd / 32;
    constexpr int NO = FUSED ? 2 : 1;
    constexpr int NT = FUSED ? 2 : 4;

    const int e = blockIdx.z;
    const bool sh = (e == E_);
    const int M = sh ? T_ : min(d_cnt[e], CAP_);
    const int m0 = blockIdx.y * 128;
    if (m0 >= M) return;
    const int n0 = blockIdx.x * (FUSED ? 64 : 128);

    const float* Asrc; const float* B1; const float* B2 = nullptr; float* Cp;
    if (FUSED) {
        Asrc = d_xr;
        B1 = sh ? wS1 : wR1 + (size_t)e * Nd * Kd;   // gate
        B2 = sh ? wS2 : wR2 + (size_t)e * Nd * Kd;   // up
        Cp = sh ? d_sinter : d_inter + (size_t)e * CAP_ * Nd;
    } else {
        Asrc = sh ? d_sinter : d_inter + (size_t)e * CAP_ * Kd;
        B1 = sh ? wS1 : wR1 + (size_t)e * Nd * Kd;
        Cp = sh ? out : d_yb + (size_t)e * CAP_ * Nd;
    }

    extern __shared__ char dsm[];
    __shared__ int srow[128];

    const int tid = threadIdx.x;
    const int wid = tid >> 5, lane = tid & 31;
    const int wr = wid >> 2, wc = wid & 3;       // warp 2x4 grid
    const int g = lane >> 2, tig = lane & 3;

    const bool gath = FUSED && !sh;
    if (gath && tid < 128) srow[tid] = (m0 + tid < M) ? d_src[e * CAP_ + m0 + tid] : 0;
    __syncthreads();

    const uint32_t smem_base = smem_u32(dsm);

    // ldmatrix per-thread pointer offsets (in floats, relative to tile base)
    const int lm_m = lane >> 3;      // matrix id 0..3
    const int lm_i = lane & 7;       // row within matrix
    // A x4: m0:(rows+0,k+0) m1:(rows+8,k+0) m2:(rows+0,k+4) m3:(rows+8,k+4)
    const int aoff = ((lm_m & 1) * 8 + lm_i) * PITCH + (lm_m >> 1) * 4;
    // B x4: m0:(rows+0,k+0) m1:(rows+0,k+4) m2:(rows+8,k+0) m3:(rows+8,k+4)
    const int boff = ((lm_m >> 1) * 8 + lm_i) * PITCH + (lm_m & 1) * 4;
    // warp-fixed row bases
    const int arowbase = wr * 64;                               // A rows
    const int brow0 = FUSED ? (wc * 16) : (wc * 32);            // B pair 0 rows
    const int brow1 = FUSED ? (64 + wc * 16) : (wc * 32 + 16);  // B pair 1 rows

    // ---- chunk loader: A and B tiles (128 rows x 32 k) via cp.async ----
    auto load_chunk = [&](int kt, int s) {
        const uint32_t sa = smem_base + (uint32_t)s * STAGE_BYTES;
        const uint32_t sbB = sa + STAGE_FLOATS * 4;
        #pragma unroll
        for (int q = 0; q < 4; q++) {
            int idx = tid + q * 256;
            int row = idx >> 3, c4 = idx & 7;
            // A
            int gr = m0 + row;
            bool v = gr < M;
            const float* gp;
            if (gath) gp = Asrc + (size_t)srow[row] * Kd + kt + c4 * 4;
            else      gp = Asrc + (size_t)(v ? gr : m0) * Kd + kt + c4 * 4;
            cp16(sa + (uint32_t)(row * PITCH + c4 * 4) * 4, gp, v);
            // B (FUSED: rows 0..63 gate, 64..127 up)
            const float* gb;
            if (FUSED) gb = (row < 64 ? B1 + (size_t)(n0 + row) * Kd
                                      : B2 + (size_t)(n0 + row - 64) * Kd) + kt + c4 * 4;
            else       gb = B1 + (size_t)(n0 + row) * Kd + kt + c4 * 4;
            cp16(sbB + (uint32_t)(row * PITCH + c4 * 4) * 4, gb, true);
        }
    };

    float acc[NO][4][NT][4];
    #pragma unroll
    for (int o = 0; o < NO; o++)
        #pragma unroll
        for (int mt = 0; mt < 4; mt++)
            #pragma unroll
            for (int nt = 0; nt < NT; nt++)
                #pragma unroll
                for (int r = 0; r < 4; r++) acc[o][mt][nt][r] = 0.f;

    load_chunk(0, 0);
    CP_COMMIT();

    for (int c = 0; c < C; c++) {
        const int s = c & 1;
        if (c + 1 < C) { load_chunk((c + 1) * 32, s ^ 1); CP_COMMIT(); CP_WAIT1(); }
        else           { CP_WAIT0(); }
        __syncthreads();

        const uint32_t Asb = smem_base + (uint32_t)s * STAGE_BYTES;
        const uint32_t Bsb = Asb + STAGE_FLOATS * 4;
        const uint32_t aAddr0 = Asb + (uint32_t)((arowbase * PITCH) + aoff) * 4;
        const uint32_t bAddr0 = Bsb + (uint32_t)((brow0 * PITCH) + boff) * 4;
        const uint32_t bAddr1 = Bsb + (uint32_t)((brow1 * PITCH) + boff) * 4;

        #pragma unroll
        for (int ks = 0; ks < 4; ks++) {
            // A fragments: 4 ldmatrix.x4 (one per mt)
            uint32_t a[4][4];
            #pragma unroll
            for (int mt = 0; mt < 4; mt++)
                ldsm_x4(a[mt][0], a[mt][1], a[mt][2], a[mt][3],
                        aAddr0 + (uint32_t)(mt * 16 * PITCH + ks * 8) * 4);
            // B fragments: 2 ldmatrix.x4 (each yields two (b0,b1) pairs), then cvt
            uint32_t bp[2][4];
            ldsm_x4(bp[0][0], bp[0][1], bp[0][2], bp[0][3], bAddr0 + (uint32_t)(ks * 8) * 4);
            ldsm_x4(bp[1][0], bp[1][1], bp[1][2], bp[1][3], bAddr1 + (uint32_t)(ks * 8) * 4);
            #pragma unroll
            for (int p = 0; p < 2; p++)
                #pragma unroll
                for (int r = 0; r < 4; r++) bp[p][r] = tf32ru(bp[p][r]);

            // map pairs to (o, nt): FUSED: pair=o, sub=nt. Down: nt = pair*2+sub.
            #pragma unroll
            for (int p = 0; p < 2; p++) {
                #pragma unroll
                for (int sub = 0; sub < 2; sub++) {
                    const uint32_t bfrag[2] = { bp[p][sub * 2], bp[p][sub * 2 + 1] };
                    const int o  = FUSED ? p : 0;
                    const int nt = FUSED ? sub : (p * 2 + sub);
                    #pragma unroll
                    for (int mt = 0; mt < 4; mt++)
                        mma_tf32(acc[o][mt][nt], a[mt], bfrag);
                }
            }
        }
        __syncthreads();
    }

    // ---- epilogue ----
    #pragma unroll
    for (int mt = 0; mt < 4; mt++) {
        #pragma unroll
        for (int nt = 0; nt < NT; nt++) {
            int r0 = m0 + wr * 64 + mt * 16 + g;
            int col = n0 + wc * (FUSED ? 16 : 32) + nt * 8 + 2 * tig;
            #pragma unroll
            for (int h = 0; h < 2; h++) {
                int r = r0 + 8 * h;
                if (r >= M) continue;
                if (FUSED) {
                    float gg0 = acc[0][mt][nt][2 * h + 0];
                    float gg1 = acc[0][mt][nt][2 * h + 1];
                    float uu0 = acc[1][mt][nt][2 * h + 0];
                    float uu1 = acc[1][mt][nt][2 * h + 1];
                    float s0 = gg0 / (1.f + expf(-gg0)) * uu0;
                    float s1 = gg1 / (1.f + expf(-gg1)) * uu1;
                    if (sh) {
                        s0 = fminf(fmaxf(s0, -10.f), 10.f);
                        s1 = fminf(fmaxf(s1, -10.f), 10.f);
                    }
                    // store pre-rounded: down pass reads A without cvt (numerically identical)
                    *(float2*)(Cp + (size_t)r * Nd + col) = make_float2(tf32f(s0), tf32f(s1));
                } else {
                    *(float2*)(Cp + (size_t)r * Nd + col) =
                        make_float2(acc[0][mt][nt][2 * h + 0], acc[0][mt][nt][2 * h + 1]);
                }
            }
        }
    }
}

// ---------------- combine: out[t] = shared(out) + sum_k w * yb[slot] ----------------
__global__ void combine_kernel(float* __restrict__ out) {
    int t = blockIdx.x;
    __shared__ int   ss[TOPK];
    __shared__ float sw[TOPK];
    if (threadIdx.x < TOPK) {
        ss[threadIdx.x] = d_slot[t * TOPK + threadIdx.x];
        sw[threadIdx.x] = d_wt[t * TOPK + threadIdx.x];
    }
    __syncthreads();
    float4* orow = (float4*)(out + (size_t)t * H_);
    for (int i = threadIdx.x; i < H_ / 4; i += blockDim.x) {
        float4 o = orow[i];
        #pragma unroll
        for (int k = 0; k < TOPK; k++) {
            int slot = ss[k];
            if (slot < 0) continue;
            float w = sw[k];
            float4 y = ((const float4*)(d_yb + (size_t)slot * H_))[i];
            o.x += w * y.x; o.y += w * y.y; o.z += w * y.z; o.w += w * y.w;
        }
        orow[i] = o;
    }
}

// ---------------- launch ----------------
extern "C" void kernel_launch(void* const* d_in, const int* in_sizes, int n_in,
                              void* d_out, int out_size) {
    const float* x      = (const float*)d_in[0];
    const float* gate_w = (const float*)d_in[1];
    const float* bias   = (const float*)d_in[2];
    const float* w_gate = (const float*)d_in[3];
    const float* w_up   = (const float*)d_in[4];
    const float* w_down = (const float*)d_in[5];
    const float* sg     = (const float*)d_in[6];
    const float* su     = (const float*)d_in[7];
    const float* sd     = (const float*)d_in[8];
    float* out = (float*)d_out;

    cudaFuncSetAttribute(gemm_tc<true>,  cudaFuncAttributeMaxDynamicSharedMemorySize, SMEM_GEMM);
    cudaFuncSetAttribute(gemm_tc<false>, cudaFuncAttributeMaxDynamicSharedMemorySize, SMEM_GEMM);

    init_kernel<<<1, 32>>>();
    round_x_kernel<<<(T_ * H_ / 4) / 256, 256>>>(x);
    router_kernel<<<T_, 128>>>(x, gate_w, bias);

    // fused gate+up (SwiGLU), then down — routed e=0..31 + shared e=32
    gemm_tc<true><<<dim3(I_ / 64, T_ / 128, E_ + 1), 256, SMEM_GEMM>>>(w_gate, w_up, sg, su, nullptr);
    gemm_tc<false><<<dim3(H_ / 128, T_ / 128, E_ + 1), 256, SMEM_GEMM>>>(w_down, nullptr, sd, nullptr, out);

    combine_kernel<<<T_, 256>>>(out);
}